// round 11
// baseline (speedup 1.0000x reference)
#include <cuda_runtime.h>
#include <cstdint>
#include <cstddef>

#define DEVI __device__ __forceinline__
typedef unsigned long long ull;

namespace {
constexpr int TT = 32, HH = 64;
constexpr int Nq = 1024;
constexpr int BN = 32 * 1024;          // 32768 sequences
constexpr int ROWS = 64;               // sequences per LSTM CTA
constexpr int NCTA = BN / ROWS;        // 512
constexpr int WP = 76;                 // padded extended-K row (76*4 B = 19*16 B)
constexpr int NCH = 18;                // 72 extended-K / 4 per chunk
constexpr int XS = TT * 5;             // 160 floats of x per sequence
// weights + 2 h-state buffers (double buffered) + x tile
constexpr int SMEM_LSTM = (256 * WP + 2 * ROWS * WP + ROWS * XS) * 4;  // 157696 B
}

// scratch (allocation-free rule: __device__ globals)
__device__ float g_eold[BN * HH];      // e_old  [B*N, 64]
__device__ float g_eq[BN * HH];        // (e_old . pw1) * e_old
__device__ float g_p0[BN];             // e_old . pred_w[0:64]
__device__ float g_coef[Nq * Nq];      // mask * leakyrelu gate
__device__ float g_deg[Nq];

// ------------------------------------------------------------------ helpers
DEVI ull ffma2(ull a, ull b, ull c) {
    ull d;
    asm("fma.rn.f32x2 %0, %1, %2, %3;" : "=l"(d) : "l"(a), "l"(b), "l"(c));
    return d;
}
DEVI ull splat2(float v) {
    ull d; unsigned u = __float_as_uint(v);
    asm("mov.b64 %0, {%1, %1};" : "=l"(d) : "r"(u));
    return d;
}
DEVI float2 unpack2(ull v) {
    float2 r;
    asm("mov.b64 {%0, %1}, %2;" : "=f"(r.x), "=f"(r.y) : "l"(v));
    return r;
}
// HW tanh (MUFU.TANH, 1 op) and sigmoid via tanh identity (1 MUFU + 2 fma-class)
DEVI float tanha(float x) {
    float y;
    asm("tanh.approx.f32 %0, %1;" : "=f"(y) : "f"(x));
    return y;
}
DEVI float siga(float x) { return fmaf(0.5f, tanha(0.5f * x), 0.5f); }

// ---------------------------------------------- Kernel 1: fused LSTM + attn + qp
// 256 threads, 64 sequences per CTA. warp rg owns rows rg*8..rg*8+7; lane jg
// owns hidden cols {jg, jg+32} for all 4 gates. Whh/Wih/bias fused as an
// extended K=72 weight matrix in SMEM; state vector = [h(64), x_t(5), 1, 0pad].
// Double-buffered state => single __syncthreads per timestep, so gate MUFU /
// attention SHFL work overlaps other warps' FFMA2 GEMM.
__global__ void __launch_bounds__(256, 1)
lstm_attn_kernel(const float* __restrict__ x,
                 const float* __restrict__ Wih, const float* __restrict__ Whh,
                 const float* __restrict__ bih, const float* __restrict__ bhh,
                 const float* __restrict__ attw, const float* __restrict__ attb,
                 const float* __restrict__ pw)
{
    extern __shared__ float sm[];
    float* wsh = sm;                       // [256][WP]
    float* hb0 = sm + 256 * WP;            // [ROWS][WP] state buffer 0
    float* hb1 = hb0 + ROWS * WP;          // [ROWS][WP] state buffer 1
    float* xsh = hb1 + ROWS * WP;          // [ROWS][160]

    const int tid = threadIdx.x;
    const int jg = tid & 31;
    const int rg = tid >> 5;
    const int seq0 = blockIdx.x * ROWS;

    // ---- stage extended weights: [Whh(64) | Wih(5) | bias | zeros]
    {
        const int col = tid;
        const float* wr = Whh + col * 64;
        float* d = wsh + col * WP;
        #pragma unroll
        for (int k = 0; k < 16; k++)
            reinterpret_cast<float4*>(d)[k] = reinterpret_cast<const float4*>(wr)[k];
        #pragma unroll
        for (int f = 0; f < 5; f++) d[64 + f] = Wih[col * 5 + f];
        d[69] = bih[col] + bhh[col];
        #pragma unroll
        for (int k = 70; k < WP; k++) d[k] = 0.f;
    }
    // ---- stage x tile [64][160] (contiguous for this CTA's rows)
    {
        const float4* xg = reinterpret_cast<const float4*>(x + (size_t)seq0 * XS);
        float4* xd = reinterpret_cast<float4*>(xsh);
        #pragma unroll
        for (int i = tid; i < ROWS * XS / 4; i += 256) xd[i] = xg[i];
    }
    for (int i = tid; i < 2 * ROWS * WP; i += 256) hb0[i] = 0.f;  // both buffers
    __syncthreads();
    if (tid < ROWS) {
        hb0[tid * WP + 69] = 1.f;                              // bias slots
        hb1[tid * WP + 69] = 1.f;
        #pragma unroll
        for (int f = 0; f < 5; f++) hb0[tid * WP + 64 + f] = xsh[tid * XS + f];
    }
    __syncthreads();

    const float aw0 = attw[jg], aw1 = attw[jg + 32], ab = attb[0];

    float c_[2][8], num[2][8], den[8];
    #pragma unroll
    for (int jj = 0; jj < 2; jj++)
        #pragma unroll
        for (int r = 0; r < 8; r++) { c_[jj][r] = 0.f; num[jj][r] = 0.f; }
    #pragma unroll
    for (int r = 0; r < 8; r++) den[r] = 0.f;

    for (int t = 0; t < TT; t++) {
        float* rb = (t & 1) ? hb1 : hb0;   // state S_t
        float* wb = (t & 1) ? hb0 : hb1;   // state S_{t+1}

        // ---- GEMM: gates[64 x 256] = state[64 x 72] @ Wext^T, FFMA2-packed
        ull acc[4][2][8];
        #pragma unroll
        for (int g = 0; g < 4; g++)
            #pragma unroll
            for (int jj = 0; jj < 2; jj++)
                #pragma unroll
                for (int r = 0; r < 8; r++) acc[g][jj][r] = 0ull;

        const float* hbase = rb + (rg * 8) * WP;
        const float* wbase = wsh + jg * WP;
        #pragma unroll 1
        for (int k4 = 0; k4 < NCH; k4++) {
            ulonglong2 hv[8];
            #pragma unroll
            for (int r = 0; r < 8; r++)
                hv[r] = *reinterpret_cast<const ulonglong2*>(hbase + r * WP + k4 * 4);
            #pragma unroll
            for (int g = 0; g < 4; g++) {
                #pragma unroll
                for (int jj = 0; jj < 2; jj++) {
                    ulonglong2 wv = *reinterpret_cast<const ulonglong2*>(
                        wbase + (g * 64 + jj * 32) * WP + k4 * 4);
                    #pragma unroll
                    for (int r = 0; r < 8; r++) {
                        acc[g][jj][r] = ffma2(hv[r].x, wv.x, acc[g][jj][r]);
                        acc[g][jj][r] = ffma2(hv[r].y, wv.y, acc[g][jj][r]);
                    }
                }
            }
        }

        // ---- gate nonlinearities (HW tanh), state update, write h_{t+1} to wb
        float hn[2][8];
        #pragma unroll
        for (int jj = 0; jj < 2; jj++)
            #pragma unroll
            for (int r = 0; r < 8; r++) {
                float2 p;
                p = unpack2(acc[0][jj][r]); float gi = p.x + p.y;
                p = unpack2(acc[1][jj][r]); float gf = p.x + p.y;
                p = unpack2(acc[2][jj][r]); float gg = p.x + p.y;
                p = unpack2(acc[3][jj][r]); float go = p.x + p.y;
                float cc = siga(gf) * c_[jj][r] + siga(gi) * tanha(gg);
                c_[jj][r] = cc;
                float h = siga(go) * tanha(cc);
                hn[jj][r] = h;
                wb[(rg * 8 + r) * WP + jj * 32 + jg] = h;
            }
        if (t + 1 < TT && jg < 5) {
            #pragma unroll
            for (int r = 0; r < 8; r++) {
                int m = rg * 8 + r;
                wb[m * WP + 64 + jg] = xsh[m * XS + (t + 1) * 5 + jg];
            }
        }

        // ---- online softmax attention (registers only; tanh-bounded => stable)
        #pragma unroll
        for (int r = 0; r < 8; r++) {
            float pr = hn[0][r] * aw0 + hn[1][r] * aw1;
            #pragma unroll
            for (int o = 16; o; o >>= 1)
                pr += __shfl_xor_sync(0xffffffffu, pr, o);
            float e = __expf(tanha(pr + ab));
            den[r] += e;
            num[0][r] = fmaf(e, hn[0][r], num[0][r]);
            num[1][r] = fmaf(e, hn[1][r], num[1][r]);
        }
        __syncthreads();   // S_{t+1} complete; reads of S_t done
    }

    // ---- epilogue: e_old, p0 = e.pw0, Eq = (e.pw1)*e
    const float pw0a = pw[jg],      pw0b = pw[jg + 32];
    const float pw1a = pw[64 + jg], pw1b = pw[96 + jg];
    #pragma unroll
    for (int r = 0; r < 8; r++) {
        const int seq = seq0 + rg * 8 + r;
        const float inv = __fdividef(1.f, den[r]);
        const float e0 = num[0][r] * inv;
        const float e1 = num[1][r] * inv;
        g_eold[(size_t)seq * HH + jg]      = e0;
        g_eold[(size_t)seq * HH + jg + 32] = e1;
        float s0 = e0 * pw0a + e1 * pw0b;
        float s1 = e0 * pw1a + e1 * pw1b;
        #pragma unroll
        for (int o = 16; o; o >>= 1) {
            s0 += __shfl_xor_sync(0xffffffffu, s0, o);
            s1 += __shfl_xor_sync(0xffffffffu, s1, o);
        }
        if (jg == 0) g_p0[seq] = s0;
        g_eq[(size_t)seq * HH + jg]      = s1 * e0;
        g_eq[(size_t)seq * HH + jg + 32] = s1 * e1;
    }
}

// --------------------------------------- Kernel 2: edge gate coef + degree
__global__ void __launch_bounds__(256)
coef_kernel(const float* __restrict__ A, const float* __restrict__ gw,
            const float* __restrict__ gb)
{
    const int i = blockIdx.x;
    const int tid = threadIdx.x;
    float w[5];
    #pragma unroll
    for (int r = 0; r < 5; r++) w[r] = gw[r];
    const float b = gb[0];
    float dsum = 0.f;
    for (int j = tid; j < Nq; j += 256) {
        const float* a = A + ((size_t)i * Nq + j) * 5;
        float s = 0.f, v = b;
        #pragma unroll
        for (int r = 0; r < 5; r++) { float ar = __ldg(a + r); s += ar; v = fmaf(ar, w[r], v); }
        float lr = v > 0.f ? v : 0.2f * v;   // LeakyReLU(0.2)
        float m  = s > 0.f ? 1.f : 0.f;      // active edge mask
        g_coef[(size_t)i * Nq + j] = m * lr;
        dsum += m;
    }
    __shared__ float red[8];
    #pragma unroll
    for (int o = 16; o; o >>= 1) dsum += __shfl_xor_sync(0xffffffffu, dsum, o);
    if ((tid & 31) == 0) red[tid >> 5] = dsum;
    __syncthreads();
    if (tid == 0) {
        float s = 0.f;
        #pragma unroll
        for (int k = 0; k < 8; k++) s += red[k];
        g_deg[i] = s;
    }
}

// ------------------- Kernel 3: M = coef @ Eq, fused pred epilogue (no e_new)
// 128 threads; thread tile = 4 i-rows (ty 0..15) x 8 h (tx 0..7).
// Per j: 4 scalar sc loads + 2 LDS.128 feed 16 FFMA2 -> FMA-bound.
namespace { constexpr int SCP = 68; }   // sc row pad (float4-aligned, bank-safe)

__global__ void __launch_bounds__(128)
gnn_kernel(const float* __restrict__ pbias, float* __restrict__ out)
{
    __shared__ __align__(16) float sc[64 * SCP];   // coef tile [64 i][64 j]
    __shared__ __align__(16) float se[64 * 64];    // Eq tile   [64 j][64 h]
    const int b  = blockIdx.y;
    const int i0 = blockIdx.x * 64;
    const int tid = threadIdx.x;
    const int tx = tid & 7, ty = tid >> 3;

    ull acc[4][4];
    #pragma unroll
    for (int r = 0; r < 4; r++)
        #pragma unroll
        for (int p = 0; p < 4; p++) acc[r][p] = 0ull;

    for (int jc = 0; jc < 16; jc++) {
        {   // stage: sc rows (64 floats each, padded) + se (contiguous 4096 floats)
            const float4* cs = reinterpret_cast<const float4*>(
                g_coef + (size_t)i0 * Nq + jc * 64);
            const float4* es = reinterpret_cast<const float4*>(
                g_eq + ((size_t)b * Nq + jc * 64) * HH);
            float4* scp = reinterpret_cast<float4*>(sc);
            float4* sep = reinterpret_cast<float4*>(se);
            #pragma unroll
            for (int idx = tid; idx < 1024; idx += 128) {
                int r = idx >> 4, c4 = idx & 15;
                scp[r * (SCP / 4) + c4] = cs[(size_t)r * (Nq / 4) + c4];
                sep[idx] = es[idx];
            }
        }
        __syncthreads();
        #pragma unroll 4
        for (int j = 0; j < 64; j++) {
            ull cs0 = splat2(sc[(ty * 4 + 0) * SCP + j]);
            ull cs1 = splat2(sc[(ty * 4 + 1) * SCP + j]);
            ull cs2 = splat2(sc[(ty * 4 + 2) * SCP + j]);
            ull cs3 = splat2(sc[(ty * 4 + 3) * SCP + j]);
            ulonglong2 e0 = *reinterpret_cast<const ulonglong2*>(se + j * 64 + tx * 8);
            ulonglong2 e1 = *reinterpret_cast<const ulonglong2*>(se + j * 64 + tx * 8 + 4);
            acc[0][0] = ffma2(cs0, e0.x, acc[0][0]);
            acc[0][1] = ffma2(cs0, e0.y, acc[0][1]);
            acc[0][2] = ffma2(cs0, e1.x, acc[0][2]);
            acc[0][3] = ffma2(cs0, e1.y, acc[0][3]);
            acc[1][0] = ffma2(cs1, e0.x, acc[1][0]);
            acc[1][1] = ffma2(cs1, e0.y, acc[1][1]);
            acc[1][2] = ffma2(cs1, e1.x, acc[1][2]);
            acc[1][3] = ffma2(cs1, e1.y, acc[1][3]);
            acc[2][0] = ffma2(cs2, e0.x, acc[2][0]);
            acc[2][1] = ffma2(cs2, e0.y, acc[2][1]);
            acc[2][2] = ffma2(cs2, e1.x, acc[2][2]);
            acc[2][3] = ffma2(cs2, e1.y, acc[2][3]);
            acc[3][0] = ffma2(cs3, e0.x, acc[3][0]);
            acc[3][1] = ffma2(cs3, e0.y, acc[3][1]);
            acc[3][2] = ffma2(cs3, e1.x, acc[3][2]);
            acc[3][3] = ffma2(cs3, e1.y, acc[3][3]);
        }
        __syncthreads();
    }

    const float pb = pbias[0];
    #pragma unroll
    for (int r = 0; r < 4; r++) {
        const int i = i0 + ty * 4 + r;
        const float* e = g_eold + ((size_t)b * Nq + i) * HH + tx * 8;
        float dot = 0.f;
        #pragma unroll
        for (int p = 0; p < 4; p++) {
            float2 m = unpack2(acc[r][p]);
            dot += m.x * e[p * 2] + m.y * e[p * 2 + 1];
        }
        dot += __shfl_xor_sync(0xffffffffu, dot, 1);
        dot += __shfl_xor_sync(0xffffffffu, dot, 2);
        dot += __shfl_xor_sync(0xffffffffu, dot, 4);
        if (tx == 0)
            out[(size_t)b * Nq + i] =
                g_p0[(size_t)b * Nq + i] + dot / g_deg[i] + pb;
    }
}

// ----------------------------------------------------------------- launcher
extern "C" void kernel_launch(void* const* d_in, const int* in_sizes, int n_in,
                              void* d_out, int out_size)
{
    const float* x    = (const float*)d_in[0];
    const float* A    = (const float*)d_in[1];
    const float* Wih  = (const float*)d_in[2];
    const float* Whh  = (const float*)d_in[3];
    const float* bih  = (const float*)d_in[4];
    const float* bhh  = (const float*)d_in[5];
    const float* attw = (const float*)d_in[6];
    const float* attb = (const float*)d_in[7];
    const float* gw   = (const float*)d_in[8];
    const float* gb   = (const float*)d_in[9];
    const float* pw   = (const float*)d_in[10];
    const float* pb   = (const float*)d_in[11];
    float* out = (float*)d_out;

    cudaFuncSetAttribute(lstm_attn_kernel,
                         cudaFuncAttributeMaxDynamicSharedMemorySize, SMEM_LSTM);

    lstm_attn_kernel<<<NCTA, 256, SMEM_LSTM>>>(x, Wih, Whh, bih, bhh, attw, attb, pw);
    coef_kernel<<<Nq, 256>>>(A, gw, gb);
    gnn_kernel<<<dim3(16, 32), 128>>>(pb, out);
}

// round 12
// speedup vs baseline: 1.0272x; 1.0272x over previous
#include <cuda_runtime.h>
#include <cstdint>
#include <cstddef>

#define DEVI __device__ __forceinline__
typedef unsigned long long ull;

namespace {
constexpr int TT = 32, HH = 64;
constexpr int Nq = 1024;
constexpr int BN = 32 * 1024;          // 32768 sequences
constexpr int ROWS = 64;               // sequences per LSTM CTA
constexpr int NCTA = BN / ROWS;        // 512
constexpr int NTHR = 512;              // 16 warps, 4 rows/warp
constexpr int RPW = 4;                 // rows per warp
constexpr int WP = 76;                 // padded extended-K row (76*4 B = 19*16 B)
constexpr int NCH = 18;                // 72 extended-K / 4 per chunk
constexpr int XS = TT * 5;             // 160 floats of x per sequence
// weights + 2 h-state buffers (double buffered) + x tile
constexpr int SMEM_LSTM = (256 * WP + 2 * ROWS * WP + ROWS * XS) * 4;  // 157696 B
}

// scratch (allocation-free rule: __device__ globals)
__device__ float g_eold[BN * HH];      // e_old  [B*N, 64]
__device__ float g_eq[BN * HH];        // (e_old . pw1) * e_old
__device__ float g_p0[BN];             // e_old . pred_w[0:64]
__device__ float g_coef[Nq * Nq];      // mask * leakyrelu gate
__device__ float g_deg[Nq];

// ------------------------------------------------------------------ helpers
DEVI ull ffma2(ull a, ull b, ull c) {
    ull d;
    asm("fma.rn.f32x2 %0, %1, %2, %3;" : "=l"(d) : "l"(a), "l"(b), "l"(c));
    return d;
}
DEVI ull splat2(float v) {
    ull d; unsigned u = __float_as_uint(v);
    asm("mov.b64 %0, {%1, %1};" : "=l"(d) : "r"(u));
    return d;
}
DEVI float2 unpack2(ull v) {
    float2 r;
    asm("mov.b64 {%0, %1}, %2;" : "=f"(r.x), "=f"(r.y) : "l"(v));
    return r;
}
// HW tanh (MUFU.TANH) and sigmoid via tanh identity
DEVI float tanha(float x) {
    float y;
    asm("tanh.approx.f32 %0, %1;" : "=f"(y) : "f"(x));
    return y;
}
DEVI float siga(float x) { return fmaf(0.5f, tanha(0.5f * x), 0.5f); }

// ---------------------------------------------- Kernel 1: fused LSTM + attn + qp
// 512 threads (16 warps), 64 sequences per CTA; warp rg owns rows rg*4..rg*4+3,
// lane jg owns hidden cols {jg, jg+32} for all 4 gates. 4 warps/SMSP gives the
// latency hiding that the 256-thread version lacked (issue was 44%).
// Whh/Wih/bias fused as an extended K=72 weight matrix in SMEM; state vector =
// [h(64), x_t(5), 1, 0pad]; double-buffered state => 1 barrier per step.
__global__ void __launch_bounds__(NTHR, 1)
lstm_attn_kernel(const float* __restrict__ x,
                 const float* __restrict__ Wih, const float* __restrict__ Whh,
                 const float* __restrict__ bih, const float* __restrict__ bhh,
                 const float* __restrict__ attw, const float* __restrict__ attb,
                 const float* __restrict__ pw)
{
    extern __shared__ float sm[];
    float* wsh = sm;                       // [256][WP]
    float* hb0 = sm + 256 * WP;            // [ROWS][WP] state buffer 0
    float* hb1 = hb0 + ROWS * WP;          // [ROWS][WP] state buffer 1
    float* xsh = hb1 + ROWS * WP;          // [ROWS][160]

    const int tid = threadIdx.x;
    const int jg = tid & 31;
    const int rg = tid >> 5;               // 0..15
    const int seq0 = blockIdx.x * ROWS;

    // ---- stage extended weights: [Whh(64) | Wih(5) | bias | zeros]
    if (tid < 256) {
        const int col = tid;
        const float* wr = Whh + col * 64;
        float* d = wsh + col * WP;
        #pragma unroll
        for (int k = 0; k < 16; k++)
            reinterpret_cast<float4*>(d)[k] = reinterpret_cast<const float4*>(wr)[k];
        #pragma unroll
        for (int f = 0; f < 5; f++) d[64 + f] = Wih[col * 5 + f];
        d[69] = bih[col] + bhh[col];
        #pragma unroll
        for (int k = 70; k < WP; k++) d[k] = 0.f;
    }
    // ---- stage x tile [64][160] (contiguous for this CTA's rows)
    {
        const float4* xg = reinterpret_cast<const float4*>(x + (size_t)seq0 * XS);
        float4* xd = reinterpret_cast<float4*>(xsh);
        #pragma unroll
        for (int i = tid; i < ROWS * XS / 4; i += NTHR) xd[i] = xg[i];
    }
    for (int i = tid; i < 2 * ROWS * WP; i += NTHR) hb0[i] = 0.f;  // both buffers
    __syncthreads();
    if (tid < ROWS) {
        hb0[tid * WP + 69] = 1.f;                              // bias slots
        hb1[tid * WP + 69] = 1.f;
        #pragma unroll
        for (int f = 0; f < 5; f++) hb0[tid * WP + 64 + f] = xsh[tid * XS + f];
    }
    __syncthreads();

    const float aw0 = attw[jg], aw1 = attw[jg + 32], ab = attb[0];

    float c_[2][RPW], num[2][RPW], den[RPW];
    #pragma unroll
    for (int jj = 0; jj < 2; jj++)
        #pragma unroll
        for (int r = 0; r < RPW; r++) { c_[jj][r] = 0.f; num[jj][r] = 0.f; }
    #pragma unroll
    for (int r = 0; r < RPW; r++) den[r] = 0.f;

    for (int t = 0; t < TT; t++) {
        float* rb = (t & 1) ? hb1 : hb0;   // state S_t
        float* wb = (t & 1) ? hb0 : hb1;   // state S_{t+1}

        // ---- GEMM: gates[64 x 256] = state[64 x 72] @ Wext^T, FFMA2-packed
        ull acc[4][2][RPW];
        #pragma unroll
        for (int g = 0; g < 4; g++)
            #pragma unroll
            for (int jj = 0; jj < 2; jj++)
                #pragma unroll
                for (int r = 0; r < RPW; r++) acc[g][jj][r] = 0ull;

        const float* hbase = rb + (rg * RPW) * WP;
        const float* wbase = wsh + jg * WP;
        #pragma unroll 1
        for (int k4 = 0; k4 < NCH; k4++) {
            ulonglong2 hv[RPW];
            #pragma unroll
            for (int r = 0; r < RPW; r++)
                hv[r] = *reinterpret_cast<const ulonglong2*>(hbase + r * WP + k4 * 4);
            #pragma unroll
            for (int g = 0; g < 4; g++) {
                #pragma unroll
                for (int jj = 0; jj < 2; jj++) {
                    ulonglong2 wv = *reinterpret_cast<const ulonglong2*>(
                        wbase + (g * 64 + jj * 32) * WP + k4 * 4);
                    #pragma unroll
                    for (int r = 0; r < RPW; r++) {
                        acc[g][jj][r] = ffma2(hv[r].x, wv.x, acc[g][jj][r]);
                        acc[g][jj][r] = ffma2(hv[r].y, wv.y, acc[g][jj][r]);
                    }
                }
            }
        }

        // ---- gate nonlinearities (HW tanh), state update, write h_{t+1} to wb
        float hn[2][RPW];
        #pragma unroll
        for (int jj = 0; jj < 2; jj++)
            #pragma unroll
            for (int r = 0; r < RPW; r++) {
                float2 p;
                p = unpack2(acc[0][jj][r]); float gi = p.x + p.y;
                p = unpack2(acc[1][jj][r]); float gf = p.x + p.y;
                p = unpack2(acc[2][jj][r]); float gg = p.x + p.y;
                p = unpack2(acc[3][jj][r]); float go = p.x + p.y;
                float cc = siga(gf) * c_[jj][r] + siga(gi) * tanha(gg);
                c_[jj][r] = cc;
                float h = siga(go) * tanha(cc);
                hn[jj][r] = h;
                wb[(rg * RPW + r) * WP + jj * 32 + jg] = h;
            }
        if (t + 1 < TT && jg < 5) {
            #pragma unroll
            for (int r = 0; r < RPW; r++) {
                int m = rg * RPW + r;
                wb[m * WP + 64 + jg] = xsh[m * XS + (t + 1) * 5 + jg];
            }
        }

        // ---- online softmax attention (registers only; tanh-bounded => stable)
        #pragma unroll
        for (int r = 0; r < RPW; r++) {
            float pr = hn[0][r] * aw0 + hn[1][r] * aw1;
            #pragma unroll
            for (int o = 16; o; o >>= 1)
                pr += __shfl_xor_sync(0xffffffffu, pr, o);
            float e = __expf(tanha(pr + ab));
            den[r] += e;
            num[0][r] = fmaf(e, hn[0][r], num[0][r]);
            num[1][r] = fmaf(e, hn[1][r], num[1][r]);
        }
        __syncthreads();   // S_{t+1} complete; reads of S_t done
    }

    // ---- epilogue: e_old, p0 = e.pw0, Eq = (e.pw1)*e
    const float pw0a = pw[jg],      pw0b = pw[jg + 32];
    const float pw1a = pw[64 + jg], pw1b = pw[96 + jg];
    #pragma unroll
    for (int r = 0; r < RPW; r++) {
        const int seq = seq0 + rg * RPW + r;
        const float inv = __fdividef(1.f, den[r]);
        const float e0 = num[0][r] * inv;
        const float e1 = num[1][r] * inv;
        g_eold[(size_t)seq * HH + jg]      = e0;
        g_eold[(size_t)seq * HH + jg + 32] = e1;
        float s0 = e0 * pw0a + e1 * pw0b;
        float s1 = e0 * pw1a + e1 * pw1b;
        #pragma unroll
        for (int o = 16; o; o >>= 1) {
            s0 += __shfl_xor_sync(0xffffffffu, s0, o);
            s1 += __shfl_xor_sync(0xffffffffu, s1, o);
        }
        if (jg == 0) g_p0[seq] = s0;
        g_eq[(size_t)seq * HH + jg]      = s1 * e0;
        g_eq[(size_t)seq * HH + jg + 32] = s1 * e1;
    }
}

// --------------------------------------- Kernel 2: edge gate coef + degree
__global__ void __launch_bounds__(256)
coef_kernel(const float* __restrict__ A, const float* __restrict__ gw,
            const float* __restrict__ gb)
{
    const int i = blockIdx.x;
    const int tid = threadIdx.x;
    float w[5];
    #pragma unroll
    for (int r = 0; r < 5; r++) w[r] = gw[r];
    const float b = gb[0];
    float dsum = 0.f;
    for (int j = tid; j < Nq; j += 256) {
        const float* a = A + ((size_t)i * Nq + j) * 5;
        float s = 0.f, v = b;
        #pragma unroll
        for (int r = 0; r < 5; r++) { float ar = __ldg(a + r); s += ar; v = fmaf(ar, w[r], v); }
        float lr = v > 0.f ? v : 0.2f * v;   // LeakyReLU(0.2)
        float m  = s > 0.f ? 1.f : 0.f;      // active edge mask
        g_coef[(size_t)i * Nq + j] = m * lr;
        dsum += m;
    }
    __shared__ float red[8];
    #pragma unroll
    for (int o = 16; o; o >>= 1) dsum += __shfl_xor_sync(0xffffffffu, dsum, o);
    if ((tid & 31) == 0) red[tid >> 5] = dsum;
    __syncthreads();
    if (tid == 0) {
        float s = 0.f;
        #pragma unroll
        for (int k = 0; k < 8; k++) s += red[k];
        g_deg[i] = s;
    }
}

// ------------------- Kernel 3: M = coef @ Eq, fused pred epilogue (no e_new)
// 128 threads; thread tile = 4 i-rows (ty 0..15) x 8 h (tx 0..7).
namespace { constexpr int SCP = 68; }   // sc row pad (float4-aligned, bank-safe)

__global__ void __launch_bounds__(128)
gnn_kernel(const float* __restrict__ pbias, float* __restrict__ out)
{
    __shared__ __align__(16) float sc[64 * SCP];   // coef tile [64 i][64 j]
    __shared__ __align__(16) float se[64 * 64];    // Eq tile   [64 j][64 h]
    const int b  = blockIdx.y;
    const int i0 = blockIdx.x * 64;
    const int tid = threadIdx.x;
    const int tx = tid & 7, ty = tid >> 3;

    ull acc[4][4];
    #pragma unroll
    for (int r = 0; r < 4; r++)
        #pragma unroll
        for (int p = 0; p < 4; p++) acc[r][p] = 0ull;

    for (int jc = 0; jc < 16; jc++) {
        {   // stage: sc rows (64 floats each, padded) + se (contiguous 4096 floats)
            const float4* cs = reinterpret_cast<const float4*>(
                g_coef + (size_t)i0 * Nq + jc * 64);
            const float4* es = reinterpret_cast<const float4*>(
                g_eq + ((size_t)b * Nq + jc * 64) * HH);
            float4* scp = reinterpret_cast<float4*>(sc);
            float4* sep = reinterpret_cast<float4*>(se);
            #pragma unroll
            for (int idx = tid; idx < 1024; idx += 128) {
                int r = idx >> 4, c4 = idx & 15;
                scp[r * (SCP / 4) + c4] = cs[(size_t)r * (Nq / 4) + c4];
                sep[idx] = es[idx];
            }
        }
        __syncthreads();
        #pragma unroll 4
        for (int j = 0; j < 64; j++) {
            ull cs0 = splat2(sc[(ty * 4 + 0) * SCP + j]);
            ull cs1 = splat2(sc[(ty * 4 + 1) * SCP + j]);
            ull cs2 = splat2(sc[(ty * 4 + 2) * SCP + j]);
            ull cs3 = splat2(sc[(ty * 4 + 3) * SCP + j]);
            ulonglong2 e0 = *reinterpret_cast<const ulonglong2*>(se + j * 64 + tx * 8);
            ulonglong2 e1 = *reinterpret_cast<const ulonglong2*>(se + j * 64 + tx * 8 + 4);
            acc[0][0] = ffma2(cs0, e0.x, acc[0][0]);
            acc[0][1] = ffma2(cs0, e0.y, acc[0][1]);
            acc[0][2] = ffma2(cs0, e1.x, acc[0][2]);
            acc[0][3] = ffma2(cs0, e1.y, acc[0][3]);
            acc[1][0] = ffma2(cs1, e0.x, acc[1][0]);
            acc[1][1] = ffma2(cs1, e0.y, acc[1][1]);
            acc[1][2] = ffma2(cs1, e1.x, acc[1][2]);
            acc[1][3] = ffma2(cs1, e1.y, acc[1][3]);
            acc[2][0] = ffma2(cs2, e0.x, acc[2][0]);
            acc[2][1] = ffma2(cs2, e0.y, acc[2][1]);
            acc[2][2] = ffma2(cs2, e1.x, acc[2][2]);
            acc[2][3] = ffma2(cs2, e1.y, acc[2][3]);
            acc[3][0] = ffma2(cs3, e0.x, acc[3][0]);
            acc[3][1] = ffma2(cs3, e0.y, acc[3][1]);
            acc[3][2] = ffma2(cs3, e1.x, acc[3][2]);
            acc[3][3] = ffma2(cs3, e1.y, acc[3][3]);
        }
        __syncthreads();
    }

    const float pb = pbias[0];
    #pragma unroll
    for (int r = 0; r < 4; r++) {
        const int i = i0 + ty * 4 + r;
        const float* e = g_eold + ((size_t)b * Nq + i) * HH + tx * 8;
        float dot = 0.f;
        #pragma unroll
        for (int p = 0; p < 4; p++) {
            float2 m = unpack2(acc[r][p]);
            dot += m.x * e[p * 2] + m.y * e[p * 2 + 1];
        }
        dot += __shfl_xor_sync(0xffffffffu, dot, 1);
        dot += __shfl_xor_sync(0xffffffffu, dot, 2);
        dot += __shfl_xor_sync(0xffffffffu, dot, 4);
        if (tx == 0)
            out[(size_t)b * Nq + i] =
                g_p0[(size_t)b * Nq + i] + dot / g_deg[i] + pb;
    }
}

// ----------------------------------------------------------------- launcher
extern "C" void kernel_launch(void* const* d_in, const int* in_sizes, int n_in,
                              void* d_out, int out_size)
{
    const float* x    = (const float*)d_in[0];
    const float* A    = (const float*)d_in[1];
    const float* Wih  = (const float*)d_in[2];
    const float* Whh  = (const float*)d_in[3];
    const float* bih  = (const float*)d_in[4];
    const float* bhh  = (const float*)d_in[5];
    const float* attw = (const float*)d_in[6];
    const float* attb = (const float*)d_in[7];
    const float* gw   = (const float*)d_in[8];
    const float* gb   = (const float*)d_in[9];
    const float* pw   = (const float*)d_in[10];
    const float* pb   = (const float*)d_in[11];
    float* out = (float*)d_out;

    cudaFuncSetAttribute(lstm_attn_kernel,
                         cudaFuncAttributeMaxDynamicSharedMemorySize, SMEM_LSTM);

    lstm_attn_kernel<<<NCTA, NTHR, SMEM_LSTM>>>(x, Wih, Whh, bih, bhh, attw, attb, pw);
    coef_kernel<<<Nq, 256>>>(A, gw, gb);
    gnn_kernel<<<dim3(16, 32), 128>>>(pb, out);
}